// round 16
// baseline (speedup 1.0000x reference)
#include <cuda_runtime.h>
#include <cuda_bf16.h>
#include <cstdint>

#define NPTS 512
#define DIN 8192
#define HENC 2048
#define EMBD 256
#define HDEC 2048
#define BRW 128
#define NBRANCH 2
#define ETA_F 2.0f
#define RTOL_F 1e-4f
#define ATOL_F 1e-8f
#define SPLIT1 8
#define SPLIT2 8

// ---------------- scratch ----------------
__device__ float g_h1[NPTS * HENC];
__device__ float g_lat[NPTS * EMBD];
__device__ __nv_bfloat16 g_lat_bf[NPTS * EMBD];
__device__ __nv_bfloat16 g_h2b[NPTS * HDEC];
__device__ __nv_bfloat16 g_xhi[NPTS * DIN];
__device__ __nv_bfloat16 g_xlo[NPTS * DIN];
__device__ __nv_bfloat16 g_w1hi[DIN * HENC];
__device__ __nv_bfloat16 g_w1lo[DIN * HENC];
__device__ __nv_bfloat16 g_wd1b[EMBD * HDEC];
__device__ __nv_bfloat16 g_wd2b[HDEC * DIN];
__device__ float g_part1[SPLIT1][NPTS * HENC];
__device__ float g_part2[SPLIT2][NPTS * EMBD];
__device__ float g_D[NBRANCH][NPTS * NPTS];
__device__ float g_mst[NBRANCH][NPTS - 1];
__device__ float g_mst_sorted[NBRANCH][NPTS];
__device__ float g_conn;
__device__ float g_rec;

__global__ void zero_kernel() { g_conn = 0.0f; g_rec = 0.0f; }

// ---------------- helpers ----------------
__device__ __forceinline__ void fma2(unsigned long long& d,
                                     unsigned long long a, unsigned long long b) {
    asm("fma.rn.f32x2 %0, %1, %2, %0;" : "+l"(d) : "l"(a), "l"(b));
}
__device__ __forceinline__ float plo(unsigned long long v) {
    return __uint_as_float((unsigned)(v & 0xffffffffULL));
}
__device__ __forceinline__ float phi(unsigned long long v) {
    return __uint_as_float((unsigned)(v >> 32));
}
__device__ __forceinline__ uint32_t s2u(const void* p) {
    uint32_t a;
    asm("{.reg .u64 t; cvta.to.shared.u64 t, %1; cvt.u32.u64 %0, t;}"
        : "=r"(a) : "l"(p));
    return a;
}
__device__ __forceinline__ void ldsm4(uint32_t* r, uint32_t addr) {
    asm volatile("ldmatrix.sync.aligned.m8n8.x4.shared.b16 {%0,%1,%2,%3}, [%4];"
                 : "=r"(r[0]), "=r"(r[1]), "=r"(r[2]), "=r"(r[3]) : "r"(addr));
}
__device__ __forceinline__ void ldsm4t(uint32_t* r, uint32_t addr) {
    asm volatile("ldmatrix.sync.aligned.m8n8.x4.trans.shared.b16 {%0,%1,%2,%3}, [%4];"
                 : "=r"(r[0]), "=r"(r[1]), "=r"(r[2]), "=r"(r[3]) : "r"(addr));
}
__device__ __forceinline__ void mma16816(float* c, const uint32_t* a, const uint32_t* b) {
    asm volatile(
        "mma.sync.aligned.m16n8k16.row.col.f32.bf16.bf16.f32 "
        "{%0,%1,%2,%3},{%4,%5,%6,%7},{%8,%9},{%0,%1,%2,%3};"
        : "+f"(c[0]), "+f"(c[1]), "+f"(c[2]), "+f"(c[3])
        : "r"(a[0]), "r"(a[1]), "r"(a[2]), "r"(a[3]), "r"(b[0]), "r"(b[1]));
}

// ---------------- fp32 -> (hi, lo) bf16 decomposition ----------------
__global__ __launch_bounds__(256) void cvt_split(const float* __restrict__ s,
                                                 __nv_bfloat16* __restrict__ hi,
                                                 __nv_bfloat16* __restrict__ lo, int n)
{
    int i = (blockIdx.x * 256 + threadIdx.x) * 8;
    if (i < n) {
        float4 a = *(const float4*)&s[i];
        float4 b = *(const float4*)&s[i + 4];
        __nv_bfloat16 h[8], l[8];
        float v[8] = {a.x, a.y, a.z, a.w, b.x, b.y, b.z, b.w};
        #pragma unroll
        for (int k = 0; k < 8; ++k) {
            h[k] = __float2bfloat16_rn(v[k]);
            l[k] = __float2bfloat16_rn(v[k] - __bfloat162float(h[k]));
        }
        *(uint4*)&hi[i] = *(uint4*)h;
        *(uint4*)&lo[i] = *(uint4*)l;
    }
}

// ---------------- fp32 -> bf16 (decoder weights) ----------------
__global__ __launch_bounds__(256) void cvt_bf16(const float* __restrict__ s,
                                                __nv_bfloat16* __restrict__ d, int n)
{
    int i = (blockIdx.x * 256 + threadIdx.x) * 8;
    if (i < n) {
        float4 a = *(const float4*)&s[i];
        float4 b = *(const float4*)&s[i + 4];
        __nv_bfloat162 h[4];
        h[0] = __floats2bfloat162_rn(a.x, a.y);
        h[1] = __floats2bfloat162_rn(a.z, a.w);
        h[2] = __floats2bfloat162_rn(b.x, b.y);
        h[3] = __floats2bfloat162_rn(b.z, b.w);
        *(uint4*)&d[i] = *(uint4*)h;
    }
}

// ---------------- bf16x3 tensor-core split-K GEMM (R7-proven) ----------------
// BM=128, BN=128, BK=16, 256 threads (8 warps, 4m x 2n), warp tile 32x64.
// acc += Ahi*Bhi + Ahi*Blo + Alo*Bhi. zoff shifts the k-split slice.
#define PA3 24
#define PB3 136
__global__ __launch_bounds__(256, 2) void bgemm3_split(
    const __nv_bfloat16* __restrict__ Ahi, const __nv_bfloat16* __restrict__ Alo,
    const __nv_bfloat16* __restrict__ Bhi, const __nv_bfloat16* __restrict__ Blo,
    float* __restrict__ P, int M, int N, int K, int k_len, int zoff)
{
    const int BM = 128, BN = 128, BK = 16;
    __shared__ __nv_bfloat16 As[2][2][BM * PA3];
    __shared__ __nv_bfloat16 Bs[2][2][BK * PB3];
    int tid = threadIdx.x;
    int wid = tid >> 5, lane = tid & 31;
    int wm = (wid & 3) * 32, wn = (wid >> 2) * 64;
    int bm = blockIdx.y * BM, bn = blockIdx.x * BN;
    int z = zoff + blockIdx.z;
    int kb = z * k_len;
    P += (size_t)z * M * N;

    float acc[2][8][4];
    #pragma unroll
    for (int mt = 0; mt < 2; ++mt)
        #pragma unroll
        for (int nt = 0; nt < 8; ++nt)
            #pragma unroll
            for (int e = 0; e < 4; ++e) acc[mt][nt][e] = 0.0f;

    int ar = tid >> 1, acg = tid & 1;
    int br = tid >> 4, bcg = tid & 15;

    uint32_t asbase = s2u(&As[0][0][0]);
    uint32_t bsbase = s2u(&Bs[0][0][0]);

    *(uint4*)&As[0][0][ar * PA3 + acg * 8] =
        *(const uint4*)&Ahi[(size_t)(bm + ar) * K + kb + acg * 8];
    *(uint4*)&As[0][1][ar * PA3 + acg * 8] =
        *(const uint4*)&Alo[(size_t)(bm + ar) * K + kb + acg * 8];
    *(uint4*)&Bs[0][0][br * PB3 + bcg * 8] =
        *(const uint4*)&Bhi[(size_t)(kb + br) * N + bn + bcg * 8];
    *(uint4*)&Bs[0][1][br * PB3 + bcg * 8] =
        *(const uint4*)&Blo[(size_t)(kb + br) * N + bn + bcg * 8];
    __syncthreads();

    int sub = lane >> 3, lr = lane & 7;
    int cur = 0;
    for (int k0 = 0; k0 < k_len; k0 += BK) {
        uint4 pah, pal, pbh, pbl;
        bool more = (k0 + BK) < k_len;
        if (more) {
            pah = *(const uint4*)&Ahi[(size_t)(bm + ar) * K + kb + k0 + BK + acg * 8];
            pal = *(const uint4*)&Alo[(size_t)(bm + ar) * K + kb + k0 + BK + acg * 8];
            pbh = *(const uint4*)&Bhi[(size_t)(kb + k0 + BK + br) * N + bn + bcg * 8];
            pbl = *(const uint4*)&Blo[(size_t)(kb + k0 + BK + br) * N + bn + bcg * 8];
        }
        uint32_t ah[2][4], al[2][4], bh[8][2], bl[8][2];
        #pragma unroll
        for (int mt = 0; mt < 2; ++mt) {
            int row = wm + mt * 16 + (sub & 1) * 8 + lr;
            int kc = (sub >> 1) * 8;
            ldsm4(ah[mt], asbase + (uint32_t)((cur * 2 + 0) * BM * PA3 + row * PA3 + kc) * 2);
            ldsm4(al[mt], asbase + (uint32_t)((cur * 2 + 1) * BM * PA3 + row * PA3 + kc) * 2);
        }
        #pragma unroll
        for (int ng = 0; ng < 4; ++ng) {
            int krow = (sub & 1) * 8 + lr;
            int ncol = wn + ng * 16 + (sub >> 1) * 8;
            uint32_t r4[4];
            ldsm4t(r4, bsbase + (uint32_t)((cur * 2 + 0) * BK * PB3 + krow * PB3 + ncol) * 2);
            bh[ng * 2 + 0][0] = r4[0]; bh[ng * 2 + 0][1] = r4[1];
            bh[ng * 2 + 1][0] = r4[2]; bh[ng * 2 + 1][1] = r4[3];
            ldsm4t(r4, bsbase + (uint32_t)((cur * 2 + 1) * BK * PB3 + krow * PB3 + ncol) * 2);
            bl[ng * 2 + 0][0] = r4[0]; bl[ng * 2 + 0][1] = r4[1];
            bl[ng * 2 + 1][0] = r4[2]; bl[ng * 2 + 1][1] = r4[3];
        }
        #pragma unroll
        for (int mt = 0; mt < 2; ++mt)
            #pragma unroll
            for (int nt = 0; nt < 8; ++nt) {
                mma16816(acc[mt][nt], ah[mt], bh[nt]);
                mma16816(acc[mt][nt], ah[mt], bl[nt]);
                mma16816(acc[mt][nt], al[mt], bh[nt]);
            }
        int nb = cur ^ 1;
        if (more) {
            *(uint4*)&As[nb][0][ar * PA3 + acg * 8] = pah;
            *(uint4*)&As[nb][1][ar * PA3 + acg * 8] = pal;
            *(uint4*)&Bs[nb][0][br * PB3 + bcg * 8] = pbh;
            *(uint4*)&Bs[nb][1][br * PB3 + bcg * 8] = pbl;
        }
        __syncthreads();
        cur = nb;
    }

    #pragma unroll
    for (int mt = 0; mt < 2; ++mt) {
        int row0 = bm + wm + mt * 16 + (lane >> 2);
        #pragma unroll
        for (int nt = 0; nt < 8; ++nt) {
            int col = bn + wn + nt * 8 + (lane & 3) * 2;
            #pragma unroll
            for (int h = 0; h < 2; ++h) {
                int row = row0 + h * 8;
                *(float2*)&P[(size_t)row * N + col] =
                    make_float2(acc[mt][nt][h * 2 + 0], acc[mt][nt][h * 2 + 1]);
            }
        }
    }
}

// ---------------- fp32 split-K GEMM via packed f32x2 FMA (GEMM2) -------------
#define PAD2 (2 * 64 + 2)
template<int G>
__global__ __launch_bounds__(256) void sgemm_split(
    const float* __restrict__ A, const float* __restrict__ B,
    float* __restrict__ P, int M, int N, int K, int k_len)
{
    const int BM = 64, BK = 16, BN = 64 * G;
    __shared__ __align__(16) float As2[2][BK][PAD2];
    __shared__ __align__(16) float Bs[2][BK][BN];
    int tid = threadIdx.x;
    int ty = tid >> 4, tx = tid & 15;
    int bm = blockIdx.y * BM, bn = blockIdx.x * BN;
    int kb = blockIdx.z * k_len;
    P += (size_t)blockIdx.z * M * N;

    unsigned long long acc[4][2 * G];
    #pragma unroll
    for (int r = 0; r < 4; ++r)
        #pragma unroll
        for (int c = 0; c < 2 * G; ++c) acc[r][c] = 0ULL;

    int arow = tid >> 2, ak4 = tid & 3;
    const int F4PR = BN / 4;
    int brow[G], bc[G];
    #pragma unroll
    for (int l = 0; l < G; ++l) { int idx = tid + l * 256; brow[l] = idx / F4PR; bc[l] = idx % F4PR; }

    {
        float4 v = *(const float4*)&A[(size_t)(bm + arow) * K + kb + ak4 * 4];
        As2[0][ak4 * 4 + 0][2 * arow] = v.x; As2[0][ak4 * 4 + 0][2 * arow + 1] = v.x;
        As2[0][ak4 * 4 + 1][2 * arow] = v.y; As2[0][ak4 * 4 + 1][2 * arow + 1] = v.y;
        As2[0][ak4 * 4 + 2][2 * arow] = v.z; As2[0][ak4 * 4 + 2][2 * arow + 1] = v.z;
        As2[0][ak4 * 4 + 3][2 * arow] = v.w; As2[0][ak4 * 4 + 3][2 * arow + 1] = v.w;
        #pragma unroll
        for (int l = 0; l < G; ++l)
            *(float4*)&Bs[0][brow[l]][bc[l] * 4] =
                *(const float4*)&B[(size_t)(kb + brow[l]) * N + bn + bc[l] * 4];
    }
    __syncthreads();

    int cur = 0;
    for (int k0 = 0; k0 < k_len; k0 += BK) {
        float4 pa; float4 pb[G];
        bool more = (k0 + BK) < k_len;
        if (more) {
            pa = *(const float4*)&A[(size_t)(bm + arow) * K + kb + k0 + BK + ak4 * 4];
            #pragma unroll
            for (int l = 0; l < G; ++l)
                pb[l] = *(const float4*)&B[(size_t)(kb + k0 + BK + brow[l]) * N + bn + bc[l] * 4];
        }
        #pragma unroll
        for (int k = 0; k < BK; ++k) {
            unsigned long long a2[4];
            #pragma unroll
            for (int r = 0; r < 4; ++r)
                a2[r] = *(const unsigned long long*)&As2[cur][k][2 * (ty * 4 + r)];
            #pragma unroll
            for (int g = 0; g < G; ++g) {
                unsigned long long b0 = *(const unsigned long long*)&Bs[cur][k][g * 64 + tx * 4];
                unsigned long long b1 = *(const unsigned long long*)&Bs[cur][k][g * 64 + tx * 4 + 2];
                #pragma unroll
                for (int r = 0; r < 4; ++r) {
                    fma2(acc[r][g * 2 + 0], a2[r], b0);
                    fma2(acc[r][g * 2 + 1], a2[r], b1);
                }
            }
        }
        int nb = cur ^ 1;
        if (more) {
            As2[nb][ak4 * 4 + 0][2 * arow] = pa.x; As2[nb][ak4 * 4 + 0][2 * arow + 1] = pa.x;
            As2[nb][ak4 * 4 + 1][2 * arow] = pa.y; As2[nb][ak4 * 4 + 1][2 * arow + 1] = pa.y;
            As2[nb][ak4 * 4 + 2][2 * arow] = pa.z; As2[nb][ak4 * 4 + 2][2 * arow + 1] = pa.z;
            As2[nb][ak4 * 4 + 3][2 * arow] = pa.w; As2[nb][ak4 * 4 + 3][2 * arow + 1] = pa.w;
            #pragma unroll
            for (int l = 0; l < G; ++l)
                *(float4*)&Bs[nb][brow[l]][bc[l] * 4] = pb[l];
        }
        __syncthreads();
        cur = nb;
    }

    #pragma unroll
    for (int r = 0; r < 4; ++r) {
        int row = bm + ty * 4 + r;
        #pragma unroll
        for (int g = 0; g < G; ++g) {
            int cbase = bn + g * 64 + tx * 4;
            float4 o;
            o.x = plo(acc[r][g * 2 + 0]); o.y = phi(acc[r][g * 2 + 0]);
            o.z = plo(acc[r][g * 2 + 1]); o.w = phi(acc[r][g * 2 + 1]);
            *(float4*)&P[(size_t)row * N + cbase] = o;
        }
    }
}

// ---------------- split-K reductions ----------------
__global__ __launch_bounds__(256) void red1_kernel(const float* __restrict__ bias) {
    int i = (blockIdx.x * 256 + threadIdx.x) * 4;
    float4 s = *(const float4*)&g_part1[0][i];
    #pragma unroll
    for (int p = 1; p < SPLIT1; ++p) {
        float4 v = *(const float4*)&g_part1[p][i];
        s.x += v.x; s.y += v.y; s.z += v.z; s.w += v.w;
    }
    float4 b = *(const float4*)&bias[i & (HENC - 1)];
    s.x = fmaxf(s.x + b.x, 0.0f); s.y = fmaxf(s.y + b.y, 0.0f);
    s.z = fmaxf(s.z + b.z, 0.0f); s.w = fmaxf(s.w + b.w, 0.0f);
    *(float4*)&g_h1[i] = s;
}
__global__ __launch_bounds__(256) void red2_kernel(const float* __restrict__ bias) {
    int i = (blockIdx.x * 256 + threadIdx.x) * 4;
    float4 s = *(const float4*)&g_part2[0][i];
    #pragma unroll
    for (int p = 1; p < SPLIT2; ++p) {
        float4 v = *(const float4*)&g_part2[p][i];
        s.x += v.x; s.y += v.y; s.z += v.z; s.w += v.w;
    }
    float4 b = *(const float4*)&bias[i & (EMBD - 1)];
    s.x += b.x; s.y += b.y; s.z += b.z; s.w += b.w;
    *(float4*)&g_lat[i] = s;
    __nv_bfloat162 h0 = __floats2bfloat162_rn(s.x, s.y);
    __nv_bfloat162 h1 = __floats2bfloat162_rn(s.z, s.w);
    *(uint2*)&g_lat_bf[i] = make_uint2(*(uint32_t*)&h0, *(uint32_t*)&h1);
}

// ---------------- bf16 tensor-core GEMM (decoder; bf16 B) ----------------
#define PA 40
#define PB 136
template<bool MSE>
__global__ __launch_bounds__(256) void bgemm_b16(
    const __nv_bfloat16* __restrict__ A, const __nv_bfloat16* __restrict__ B,
    const float* __restrict__ bias, __nv_bfloat16* __restrict__ Cb,
    const float* __restrict__ X, int M, int N, int K)
{
    const int BM = 128, BN = 128, BK = 32;
    __shared__ __nv_bfloat16 As[2][BM * PA];
    __shared__ __nv_bfloat16 Bs[2][BK * PB];
    int tid = threadIdx.x;
    int wid = tid >> 5, lane = tid & 31;
    int wm = (wid & 3) * 32, wn = (wid >> 2) * 64;
    int bm = blockIdx.y * BM, bn = blockIdx.x * BN;

    float acc[2][8][4];
    #pragma unroll
    for (int mt = 0; mt < 2; ++mt)
        #pragma unroll
        for (int nt = 0; nt < 8; ++nt)
            #pragma unroll
            for (int e = 0; e < 4; ++e) acc[mt][nt][e] = 0.0f;

    int ar[2], acg[2];
    #pragma unroll
    for (int l = 0; l < 2; ++l) { int idx = tid + l * 256; ar[l] = idx >> 2; acg[l] = idx & 3; }
    int br[2], bcg[2];
    #pragma unroll
    for (int l = 0; l < 2; ++l) { int idx = tid + l * 256; br[l] = idx >> 4; bcg[l] = idx & 15; }

    uint32_t asbase = s2u(&As[0][0]);
    uint32_t bsbase = s2u(&Bs[0][0]);

    #pragma unroll
    for (int l = 0; l < 2; ++l) {
        *(uint4*)&As[0][ar[l] * PA + acg[l] * 8] =
            *(const uint4*)&A[(size_t)(bm + ar[l]) * K + acg[l] * 8];
        *(uint4*)&Bs[0][br[l] * PB + bcg[l] * 8] =
            *(const uint4*)&B[(size_t)br[l] * N + bn + bcg[l] * 8];
    }
    __syncthreads();

    int sub = lane >> 3, lr = lane & 7;
    int cur = 0;
    for (int k0 = 0; k0 < K; k0 += BK) {
        uint4 pa[2], pb[2];
        bool more = (k0 + BK) < K;
        if (more) {
            #pragma unroll
            for (int l = 0; l < 2; ++l) {
                pa[l] = *(const uint4*)&A[(size_t)(bm + ar[l]) * K + k0 + BK + acg[l] * 8];
                pb[l] = *(const uint4*)&B[(size_t)(k0 + BK + br[l]) * N + bn + bcg[l] * 8];
            }
        }
        #pragma unroll
        for (int ks = 0; ks < BK; ks += 16) {
            uint32_t a[2][4], b[8][2];
            #pragma unroll
            for (int mt = 0; mt < 2; ++mt) {
                int row = wm + mt * 16 + (sub & 1) * 8 + lr;
                int kc = ks + (sub >> 1) * 8;
                ldsm4(a[mt], asbase + (uint32_t)(cur * BM * PA + row * PA + kc) * 2);
            }
            #pragma unroll
            for (int ng = 0; ng < 4; ++ng) {
                uint32_t r4[4];
                int krow = ks + (sub & 1) * 8 + lr;
                int ncol = wn + ng * 16 + (sub >> 1) * 8;
                ldsm4t(r4, bsbase + (uint32_t)(cur * BK * PB + krow * PB + ncol) * 2);
                b[ng * 2 + 0][0] = r4[0]; b[ng * 2 + 0][1] = r4[1];
                b[ng * 2 + 1][0] = r4[2]; b[ng * 2 + 1][1] = r4[3];
            }
            #pragma unroll
            for (int mt = 0; mt < 2; ++mt)
                #pragma unroll
                for (int nt = 0; nt < 8; ++nt)
                    mma16816(acc[mt][nt], a[mt], b[nt]);
        }
        int nb = cur ^ 1;
        if (more) {
            #pragma unroll
            for (int l = 0; l < 2; ++l) {
                *(uint4*)&As[nb][ar[l] * PA + acg[l] * 8] = pa[l];
                *(uint4*)&Bs[nb][br[l] * PB + bcg[l] * 8] = pb[l];
            }
        }
        __syncthreads();
        cur = nb;
    }

    float lsum = 0.0f;
    #pragma unroll
    for (int mt = 0; mt < 2; ++mt) {
        int row0 = bm + wm + mt * 16 + (lane >> 2);
        #pragma unroll
        for (int nt = 0; nt < 8; ++nt) {
            int col = bn + wn + nt * 8 + (lane & 3) * 2;
            float b0 = bias[col], b1 = bias[col + 1];
            #pragma unroll
            for (int h = 0; h < 2; ++h) {
                int row = row0 + h * 8;
                float v0 = acc[mt][nt][h * 2 + 0] + b0;
                float v1 = acc[mt][nt][h * 2 + 1] + b1;
                if (!MSE) {
                    v0 = fmaxf(v0, 0.0f); v1 = fmaxf(v1, 0.0f);
                    *(__nv_bfloat162*)&Cb[(size_t)row * N + col] = __floats2bfloat162_rn(v0, v1);
                } else {
                    float2 xv = *(const float2*)&X[(size_t)row * N + col];
                    float d0 = xv.x - v0, d1 = xv.y - v1;
                    lsum = fmaf(d0, d0, lsum);
                    lsum = fmaf(d1, d1, lsum);
                }
            }
        }
    }
    if (MSE) {
        #pragma unroll
        for (int o = 16; o > 0; o >>= 1)
            lsum += __shfl_down_sync(0xffffffffu, lsum, o);
        __shared__ float wsum[8];
        if (lane == 0) wsum[wid] = lsum;
        __syncthreads();
        if (tid == 0) {
            float s = 0.0f;
            #pragma unroll
            for (int w = 0; w < 8; ++w) s += wsum[w];
            atomicAdd(&g_rec, s);
        }
    }
}

// ---------------- pairwise distance matrix per branch ----------------
__global__ __launch_bounds__(256) void dist_kernel() {
    int brz = blockIdx.z;
    int i0 = blockIdx.y * 32, j0 = blockIdx.x * 32;
    __shared__ float Li[32][BRW + 1];
    __shared__ float Lj[32][BRW + 1];
    int t = threadIdx.x;
    #pragma unroll
    for (int l = 0; l < 4; ++l) {
        int idx = t + l * 256;
        int r = idx >> 5, c4 = idx & 31;
        float4 v = *(const float4*)&g_lat[(size_t)(i0 + r) * EMBD + brz * BRW + c4 * 4];
        Li[r][c4 * 4 + 0] = v.x; Li[r][c4 * 4 + 1] = v.y;
        Li[r][c4 * 4 + 2] = v.z; Li[r][c4 * 4 + 3] = v.w;
        float4 w = *(const float4*)&g_lat[(size_t)(j0 + r) * EMBD + brz * BRW + c4 * 4];
        Lj[r][c4 * 4 + 0] = w.x; Lj[r][c4 * 4 + 1] = w.y;
        Lj[r][c4 * 4 + 2] = w.z; Lj[r][c4 * 4 + 3] = w.w;
    }
    __syncthreads();
    int tx = t & 31, ty = t >> 5;
    #pragma unroll
    for (int ii = 0; ii < 4; ++ii) {
        int il = ty * 4 + ii;
        float acc = 0.0f;
        #pragma unroll 16
        for (int k = 0; k < BRW; ++k) {
            float d = Li[il][k] - Lj[tx][k];
            acc = fmaf(d, d, acc);
        }
        g_D[brz][(size_t)(i0 + il) * NPTS + j0 + tx] = sqrtf(acc);
    }
}

// ---------------- Boruvka MST per branch ----------------
__global__ __launch_bounds__(512) void boruvka_kernel() {
    int brz = blockIdx.x;
    const float* __restrict__ D = g_D[brz];
    int i = threadIdx.x;
    __shared__ int comp[NPTS];
    __shared__ unsigned cbw[NPTS];
    __shared__ int cbi[NPTS];
    __shared__ int cbj[NPTS];
    __shared__ int hook0[NPTS];
    __shared__ int hook[NPTS];
    __shared__ int nedges;

    comp[i] = i;
    if (i == 0) nedges = 0;

    for (int round = 0; round < 10; ++round) {
        __syncthreads();
        if (nedges >= NPTS - 1) break;
        cbw[i] = 0xFFFFFFFFu;
        cbi[i] = 0x7FFFFFFF;
        __syncthreads();

        int ci = comp[i];
        unsigned bw = 0xFFFFFFFFu; int bj = -1;
        for (int k0 = 0; k0 < NPTS; k0 += 4) {
            int4 c4 = *(const int4*)&comp[k0];
            float w0 = D[(size_t)(k0 + 0) * NPTS + i];
            float w1 = D[(size_t)(k0 + 1) * NPTS + i];
            float w2 = D[(size_t)(k0 + 2) * NPTS + i];
            float w3 = D[(size_t)(k0 + 3) * NPTS + i];
            unsigned u0 = __float_as_uint(w0), u1 = __float_as_uint(w1);
            unsigned u2 = __float_as_uint(w2), u3 = __float_as_uint(w3);
            if (c4.x != ci && u0 < bw) { bw = u0; bj = k0 + 0; }
            if (c4.y != ci && u1 < bw) { bw = u1; bj = k0 + 1; }
            if (c4.z != ci && u2 < bw) { bw = u2; bj = k0 + 2; }
            if (c4.w != ci && u3 < bw) { bw = u3; bj = k0 + 3; }
        }
        if (bj >= 0) atomicMin(&cbw[ci], bw);
        __syncthreads();
        if (bj >= 0 && bw == cbw[ci]) atomicMin(&cbi[ci], i);
        __syncthreads();
        if (bj >= 0 && bw == cbw[ci] && cbi[ci] == i) cbj[ci] = bj;
        __syncthreads();

        bool isroot = (comp[i] == i);
        if (isroot) hook0[i] = (cbw[i] != 0xFFFFFFFFu) ? comp[cbj[i]] : i;
        __syncthreads();
        if (isroot) {
            int d = hook0[i];
            if (d != i) {
                bool mutual = (hook0[d] == i);
                if (!mutual || i < d) {
                    int e = atomicAdd(&nedges, 1);
                    g_mst[brz][e] = __uint_as_float(cbw[i]);
                }
                hook[i] = (mutual && i < d) ? i : d;
            } else {
                hook[i] = i;
            }
        }
        __syncthreads();
        #pragma unroll
        for (int s = 0; s < 9; ++s) {
            int h = -1;
            if (isroot) h = hook[hook[i]];
            __syncthreads();
            if (isroot) hook[i] = h;
            __syncthreads();
        }
        comp[i] = hook[comp[i]];
    }
}

// ---------------- bitonic sort of MST lengths ----------------
__global__ __launch_bounds__(512) void sort_kernel() {
    int brz = blockIdx.x;
    __shared__ float s[NPTS];
    int t = threadIdx.x;
    s[t] = (t < NPTS - 1) ? g_mst[brz][t] : 3.402823466e38f;
    __syncthreads();
    for (int ksz = 2; ksz <= NPTS; ksz <<= 1) {
        for (int j = ksz >> 1; j > 0; j >>= 1) {
            int ixj = t ^ j;
            if (ixj > t) {
                float a = s[t], b = s[ixj];
                bool up = ((t & ksz) == 0);
                if ((a > b) == up) { s[t] = b; s[ixj] = a; }
            }
            __syncthreads();
        }
    }
    g_mst_sorted[brz][t] = s[t];
}

// ---------------- connectivity loss (binary search over sorted MST) ----------
__global__ __launch_bounds__(256) void conn_kernel() {
    int brz = blockIdx.y;
    __shared__ float s[NPTS];
    int t = threadIdx.x;
    s[t] = g_mst_sorted[brz][t];
    s[t + 256] = g_mst_sorted[brz][t + 256];
    __syncthreads();
    float lsum = 0.0f;
    for (int p = blockIdx.x * 256 + t; p < NPTS * NPTS; p += gridDim.x * 256) {
        int i = p >> 9, j = p & (NPTS - 1);
        if (j > i) {
            float d = g_D[brz][p];
            float lo = d - 0.004f, hi = d + 0.004f;
            int l = 0, r = NPTS;
            while (l < r) {
                int m = (l + r) >> 1;
                if (s[m] < lo) l = m + 1; else r = m;
            }
            bool hit = false;
            while (l < NPTS - 1 && s[l] <= hi) {
                float m = s[l];
                if (fabsf(d - m) <= ATOL_F + RTOL_F * fabsf(m)) { hit = true; break; }
                ++l;
            }
            if (hit) lsum += fabsf(ETA_F - d);
        }
    }
    #pragma unroll
    for (int o = 16; o > 0; o >>= 1)
        lsum += __shfl_down_sync(0xffffffffu, lsum, o);
    __shared__ float wsum[8];
    if ((t & 31) == 0) wsum[t >> 5] = lsum;
    __syncthreads();
    if (t == 0) {
        float ss = 0.0f;
        #pragma unroll
        for (int w = 0; w < 8; ++w) ss += wsum[w];
        atomicAdd(&g_conn, ss);
    }
}

__global__ void final_kernel(float* out) {
    out[0] = g_rec / (float)((size_t)NPTS * (size_t)DIN) + g_conn;
}

// ---------------- launch ----------------
extern "C" void kernel_launch(void* const* d_in, const int* in_sizes, int n_in,
                              void* d_out, int out_size) {
    const float* x   = (const float*)d_in[0];
    const float* We1 = (const float*)d_in[1];
    const float* be1 = (const float*)d_in[2];
    const float* We2 = (const float*)d_in[3];
    const float* be2 = (const float*)d_in[4];
    const float* Wd1 = (const float*)d_in[5];
    const float* bd1 = (const float*)d_in[6];
    const float* Wd2 = (const float*)d_in[7];
    const float* bd2 = (const float*)d_in[8];
    float* out = (float*)d_out;

    float *h1, *p1, *p2;
    __nv_bfloat16 *latb, *h2b, *xhi, *xlo, *w1hi, *w1lo, *wd1b, *wd2b;
    cudaGetSymbolAddress((void**)&h1,   g_h1);
    cudaGetSymbolAddress((void**)&p1,   g_part1);
    cudaGetSymbolAddress((void**)&p2,   g_part2);
    cudaGetSymbolAddress((void**)&latb, g_lat_bf);
    cudaGetSymbolAddress((void**)&h2b,  g_h2b);
    cudaGetSymbolAddress((void**)&xhi,  g_xhi);
    cudaGetSymbolAddress((void**)&xlo,  g_xlo);
    cudaGetSymbolAddress((void**)&w1hi, g_w1hi);
    cudaGetSymbolAddress((void**)&w1lo, g_w1lo);
    cudaGetSymbolAddress((void**)&wd1b, g_wd1b);
    cudaGetSymbolAddress((void**)&wd2b, g_wd2b);

    static cudaStream_t s_top = nullptr;
    static cudaEvent_t ev_fork0 = nullptr, ev_fork = nullptr, ev_join = nullptr,
                       ev_c0 = nullptr, ev_c1 = nullptr, ev_wd = nullptr;
    if (s_top == nullptr) {
        cudaStreamCreate(&s_top);
        cudaEventCreateWithFlags(&ev_fork0, cudaEventDisableTiming);
        cudaEventCreateWithFlags(&ev_fork,  cudaEventDisableTiming);
        cudaEventCreateWithFlags(&ev_join,  cudaEventDisableTiming);
        cudaEventCreateWithFlags(&ev_c0,    cudaEventDisableTiming);
        cudaEventCreateWithFlags(&ev_c1,    cudaEventDisableTiming);
        cudaEventCreateWithFlags(&ev_wd,    cudaEventDisableTiming);
    }

    const int HALF1 = (DIN / 2) * HENC;   // elements in half of We1

    zero_kernel<<<1, 1>>>();
    cudaEventRecord(ev_fork0, 0);
    cudaStreamWaitEvent(s_top, ev_fork0, 0);
    // side stream: We1 cvt in 2 chunks (gates the two GEMM1 halves), then
    // decoder weight cvts (hidden under GEMM1)
    cvt_split<<<HALF1 / 2048, 256, 0, s_top>>>(We1, w1hi, w1lo, HALF1);
    cudaEventRecord(ev_c0, s_top);
    cvt_split<<<HALF1 / 2048, 256, 0, s_top>>>(We1 + HALF1, w1hi + HALF1, w1lo + HALF1, HALF1);
    cudaEventRecord(ev_c1, s_top);
    cvt_bf16<<<(EMBD * HDEC) / 2048, 256, 0, s_top>>>(Wd1, wd1b, EMBD * HDEC);
    cvt_bf16<<<(HDEC * DIN) / 2048, 256, 0, s_top>>>(Wd2, wd2b, HDEC * DIN);
    cudaEventRecord(ev_wd, s_top);
    // main stream: x hi/lo cvt, then GEMM1 in two k-halves pipelined on cvt
    cvt_split<<<(NPTS * DIN) / 2048, 256>>>(x, xhi, xlo, NPTS * DIN);
    cudaStreamWaitEvent(0, ev_c0, 0);
    bgemm3_split<<<dim3(HENC / 128, NPTS / 128, SPLIT1 / 2), 256>>>(
        xhi, xlo, w1hi, w1lo, p1, NPTS, HENC, DIN, DIN / SPLIT1, 0);
    cudaStreamWaitEvent(0, ev_c1, 0);
    bgemm3_split<<<dim3(HENC / 128, NPTS / 128, SPLIT1 / 2), 256>>>(
        xhi, xlo, w1hi, w1lo, p1, NPTS, HENC, DIN, DIN / SPLIT1, SPLIT1 / 2);
    red1_kernel<<<NPTS * HENC / 1024, 256>>>(be1);
    // encoder GEMM2: fp32 FFMA2 split-K (precision safety)
    sgemm_split<1><<<dim3(EMBD / 64, NPTS / 64, SPLIT2), 256>>>(h1, We2, p2, NPTS, EMBD, HENC, HENC / SPLIT2);
    red2_kernel<<<NPTS * EMBD / 1024, 256>>>(be2);

    // fork: topology chain on side stream, decoder on main stream
    cudaEventRecord(ev_fork, 0);
    cudaStreamWaitEvent(s_top, ev_fork, 0);
    dist_kernel<<<dim3(NPTS / 32, NPTS / 32, NBRANCH), 256, 0, s_top>>>();
    boruvka_kernel<<<NBRANCH, NPTS, 0, s_top>>>();
    sort_kernel<<<NBRANCH, NPTS, 0, s_top>>>();
    conn_kernel<<<dim3(64, NBRANCH), 256, 0, s_top>>>();
    cudaEventRecord(ev_join, s_top);

    cudaStreamWaitEvent(0, ev_wd, 0);
    bgemm_b16<false><<<dim3(HDEC / 128, NPTS / 128), 256>>>(latb, wd1b, bd1, h2b, nullptr, NPTS, HDEC, EMBD);
    bgemm_b16<true ><<<dim3(DIN  / 128, NPTS / 128), 256>>>(h2b,  wd2b, bd2, nullptr, x,   NPTS, DIN,  HDEC);

    cudaStreamWaitEvent(0, ev_join, 0);
    final_kernel<<<1, 1>>>(out);
}

// round 17
// speedup vs baseline: 1.0496x; 1.0496x over previous
#include <cuda_runtime.h>
#include <cuda_bf16.h>
#include <cstdint>

#define NPTS 512
#define DIN 8192
#define HENC 2048
#define EMBD 256
#define HDEC 2048
#define BRW 128
#define NBRANCH 2
#define ETA_F 2.0f
#define RTOL_F 1e-4f
#define ATOL_F 1e-8f
#define SPLIT1 8
#define SPLIT2 8

// ---------------- scratch ----------------
__device__ float g_h1[NPTS * HENC];
__device__ float g_lat[NPTS * EMBD];
__device__ __nv_bfloat16 g_lat_bf[NPTS * EMBD];
__device__ __nv_bfloat16 g_h2b[NPTS * HDEC];
__device__ __nv_bfloat16 g_xhi[NPTS * DIN];
__device__ __nv_bfloat16 g_xlo[NPTS * DIN];
__device__ __nv_bfloat16 g_w1hi[DIN * HENC];
__device__ __nv_bfloat16 g_w1lo[DIN * HENC];
__device__ __nv_bfloat16 g_wd1b[EMBD * HDEC];
__device__ __nv_bfloat16 g_wd2b[HDEC * DIN];
__device__ float g_part1[SPLIT1][NPTS * HENC];
__device__ float g_part2[SPLIT2][NPTS * EMBD];
__device__ float g_D[NBRANCH][NPTS * NPTS];
__device__ float g_mst_sorted[NBRANCH][NPTS];
__device__ float g_conn;
__device__ float g_rec;

__global__ void zero_kernel() { g_conn = 0.0f; g_rec = 0.0f; }

// ---------------- helpers ----------------
__device__ __forceinline__ void fma2(unsigned long long& d,
                                     unsigned long long a, unsigned long long b) {
    asm("fma.rn.f32x2 %0, %1, %2, %0;" : "+l"(d) : "l"(a), "l"(b));
}
__device__ __forceinline__ float plo(unsigned long long v) {
    return __uint_as_float((unsigned)(v & 0xffffffffULL));
}
__device__ __forceinline__ float phi(unsigned long long v) {
    return __uint_as_float((unsigned)(v >> 32));
}
__device__ __forceinline__ uint32_t s2u(const void* p) {
    uint32_t a;
    asm("{.reg .u64 t; cvta.to.shared.u64 t, %1; cvt.u32.u64 %0, t;}"
        : "=r"(a) : "l"(p));
    return a;
}
__device__ __forceinline__ void ldsm4(uint32_t* r, uint32_t addr) {
    asm volatile("ldmatrix.sync.aligned.m8n8.x4.shared.b16 {%0,%1,%2,%3}, [%4];"
                 : "=r"(r[0]), "=r"(r[1]), "=r"(r[2]), "=r"(r[3]) : "r"(addr));
}
__device__ __forceinline__ void ldsm4t(uint32_t* r, uint32_t addr) {
    asm volatile("ldmatrix.sync.aligned.m8n8.x4.trans.shared.b16 {%0,%1,%2,%3}, [%4];"
                 : "=r"(r[0]), "=r"(r[1]), "=r"(r[2]), "=r"(r[3]) : "r"(addr));
}
__device__ __forceinline__ void mma16816(float* c, const uint32_t* a, const uint32_t* b) {
    asm volatile(
        "mma.sync.aligned.m16n8k16.row.col.f32.bf16.bf16.f32 "
        "{%0,%1,%2,%3},{%4,%5,%6,%7},{%8,%9},{%0,%1,%2,%3};"
        : "+f"(c[0]), "+f"(c[1]), "+f"(c[2]), "+f"(c[3])
        : "r"(a[0]), "r"(a[1]), "r"(a[2]), "r"(a[3]), "r"(b[0]), "r"(b[1]));
}

// ---------------- fp32 -> (hi, lo) bf16 decomposition ----------------
__global__ __launch_bounds__(256) void cvt_split(const float* __restrict__ s,
                                                 __nv_bfloat16* __restrict__ hi,
                                                 __nv_bfloat16* __restrict__ lo, int n)
{
    int i = (blockIdx.x * 256 + threadIdx.x) * 8;
    if (i < n) {
        float4 a = *(const float4*)&s[i];
        float4 b = *(const float4*)&s[i + 4];
        __nv_bfloat16 h[8], l[8];
        float v[8] = {a.x, a.y, a.z, a.w, b.x, b.y, b.z, b.w};
        #pragma unroll
        for (int k = 0; k < 8; ++k) {
            h[k] = __float2bfloat16_rn(v[k]);
            l[k] = __float2bfloat16_rn(v[k] - __bfloat162float(h[k]));
        }
        *(uint4*)&hi[i] = *(uint4*)h;
        *(uint4*)&lo[i] = *(uint4*)l;
    }
}

// ---------------- fp32 -> bf16 (decoder weights) ----------------
__global__ __launch_bounds__(256) void cvt_bf16(const float* __restrict__ s,
                                                __nv_bfloat16* __restrict__ d, int n)
{
    int i = (blockIdx.x * 256 + threadIdx.x) * 8;
    if (i < n) {
        float4 a = *(const float4*)&s[i];
        float4 b = *(const float4*)&s[i + 4];
        __nv_bfloat162 h[4];
        h[0] = __floats2bfloat162_rn(a.x, a.y);
        h[1] = __floats2bfloat162_rn(a.z, a.w);
        h[2] = __floats2bfloat162_rn(b.x, b.y);
        h[3] = __floats2bfloat162_rn(b.z, b.w);
        *(uint4*)&d[i] = *(uint4*)h;
    }
}

// ---------------- bf16x3 tensor-core split-K GEMM (R7-proven) ----------------
#define PA3 24
#define PB3 136
__global__ __launch_bounds__(256, 2) void bgemm3_split(
    const __nv_bfloat16* __restrict__ Ahi, const __nv_bfloat16* __restrict__ Alo,
    const __nv_bfloat16* __restrict__ Bhi, const __nv_bfloat16* __restrict__ Blo,
    float* __restrict__ P, int M, int N, int K, int k_len)
{
    const int BM = 128, BN = 128, BK = 16;
    __shared__ __nv_bfloat16 As[2][2][BM * PA3];
    __shared__ __nv_bfloat16 Bs[2][2][BK * PB3];
    int tid = threadIdx.x;
    int wid = tid >> 5, lane = tid & 31;
    int wm = (wid & 3) * 32, wn = (wid >> 2) * 64;
    int bm = blockIdx.y * BM, bn = blockIdx.x * BN;
    int kb = blockIdx.z * k_len;
    P += (size_t)blockIdx.z * M * N;

    float acc[2][8][4];
    #pragma unroll
    for (int mt = 0; mt < 2; ++mt)
        #pragma unroll
        for (int nt = 0; nt < 8; ++nt)
            #pragma unroll
            for (int e = 0; e < 4; ++e) acc[mt][nt][e] = 0.0f;

    int ar = tid >> 1, acg = tid & 1;
    int br = tid >> 4, bcg = tid & 15;

    uint32_t asbase = s2u(&As[0][0][0]);
    uint32_t bsbase = s2u(&Bs[0][0][0]);

    *(uint4*)&As[0][0][ar * PA3 + acg * 8] =
        *(const uint4*)&Ahi[(size_t)(bm + ar) * K + kb + acg * 8];
    *(uint4*)&As[0][1][ar * PA3 + acg * 8] =
        *(const uint4*)&Alo[(size_t)(bm + ar) * K + kb + acg * 8];
    *(uint4*)&Bs[0][0][br * PB3 + bcg * 8] =
        *(const uint4*)&Bhi[(size_t)(kb + br) * N + bn + bcg * 8];
    *(uint4*)&Bs[0][1][br * PB3 + bcg * 8] =
        *(const uint4*)&Blo[(size_t)(kb + br) * N + bn + bcg * 8];
    __syncthreads();

    int sub = lane >> 3, lr = lane & 7;
    int cur = 0;
    for (int k0 = 0; k0 < k_len; k0 += BK) {
        uint4 pah, pal, pbh, pbl;
        bool more = (k0 + BK) < k_len;
        if (more) {
            pah = *(const uint4*)&Ahi[(size_t)(bm + ar) * K + kb + k0 + BK + acg * 8];
            pal = *(const uint4*)&Alo[(size_t)(bm + ar) * K + kb + k0 + BK + acg * 8];
            pbh = *(const uint4*)&Bhi[(size_t)(kb + k0 + BK + br) * N + bn + bcg * 8];
            pbl = *(const uint4*)&Blo[(size_t)(kb + k0 + BK + br) * N + bn + bcg * 8];
        }
        uint32_t ah[2][4], al[2][4], bh[8][2], bl[8][2];
        #pragma unroll
        for (int mt = 0; mt < 2; ++mt) {
            int row = wm + mt * 16 + (sub & 1) * 8 + lr;
            int kc = (sub >> 1) * 8;
            ldsm4(ah[mt], asbase + (uint32_t)((cur * 2 + 0) * BM * PA3 + row * PA3 + kc) * 2);
            ldsm4(al[mt], asbase + (uint32_t)((cur * 2 + 1) * BM * PA3 + row * PA3 + kc) * 2);
        }
        #pragma unroll
        for (int ng = 0; ng < 4; ++ng) {
            int krow = (sub & 1) * 8 + lr;
            int ncol = wn + ng * 16 + (sub >> 1) * 8;
            uint32_t r4[4];
            ldsm4t(r4, bsbase + (uint32_t)((cur * 2 + 0) * BK * PB3 + krow * PB3 + ncol) * 2);
            bh[ng * 2 + 0][0] = r4[0]; bh[ng * 2 + 0][1] = r4[1];
            bh[ng * 2 + 1][0] = r4[2]; bh[ng * 2 + 1][1] = r4[3];
            ldsm4t(r4, bsbase + (uint32_t)((cur * 2 + 1) * BK * PB3 + krow * PB3 + ncol) * 2);
            bl[ng * 2 + 0][0] = r4[0]; bl[ng * 2 + 0][1] = r4[1];
            bl[ng * 2 + 1][0] = r4[2]; bl[ng * 2 + 1][1] = r4[3];
        }
        #pragma unroll
        for (int mt = 0; mt < 2; ++mt)
            #pragma unroll
            for (int nt = 0; nt < 8; ++nt) {
                mma16816(acc[mt][nt], ah[mt], bh[nt]);
                mma16816(acc[mt][nt], ah[mt], bl[nt]);
                mma16816(acc[mt][nt], al[mt], bh[nt]);
            }
        int nb = cur ^ 1;
        if (more) {
            *(uint4*)&As[nb][0][ar * PA3 + acg * 8] = pah;
            *(uint4*)&As[nb][1][ar * PA3 + acg * 8] = pal;
            *(uint4*)&Bs[nb][0][br * PB3 + bcg * 8] = pbh;
            *(uint4*)&Bs[nb][1][br * PB3 + bcg * 8] = pbl;
        }
        __syncthreads();
        cur = nb;
    }

    #pragma unroll
    for (int mt = 0; mt < 2; ++mt) {
        int row0 = bm + wm + mt * 16 + (lane >> 2);
        #pragma unroll
        for (int nt = 0; nt < 8; ++nt) {
            int col = bn + wn + nt * 8 + (lane & 3) * 2;
            #pragma unroll
            for (int h = 0; h < 2; ++h) {
                int row = row0 + h * 8;
                *(float2*)&P[(size_t)row * N + col] =
                    make_float2(acc[mt][nt][h * 2 + 0], acc[mt][nt][h * 2 + 1]);
            }
        }
    }
}

// ---------------- fp32 split-K GEMM via packed f32x2 FMA (GEMM2) -------------
#define PAD2 (2 * 64 + 2)
template<int G>
__global__ __launch_bounds__(256) void sgemm_split(
    const float* __restrict__ A, const float* __restrict__ B,
    float* __restrict__ P, int M, int N, int K, int k_len)
{
    const int BM = 64, BK = 16, BN = 64 * G;
    __shared__ __align__(16) float As2[2][BK][PAD2];
    __shared__ __align__(16) float Bs[2][BK][BN];
    int tid = threadIdx.x;
    int ty = tid >> 4, tx = tid & 15;
    int bm = blockIdx.y * BM, bn = blockIdx.x * BN;
    int kb = blockIdx.z * k_len;
    P += (size_t)blockIdx.z * M * N;

    unsigned long long acc[4][2 * G];
    #pragma unroll
    for (int r = 0; r < 4; ++r)
        #pragma unroll
        for (int c = 0; c < 2 * G; ++c) acc[r][c] = 0ULL;

    int arow = tid >> 2, ak4 = tid & 3;
    const int F4PR = BN / 4;
    int brow[G], bc[G];
    #pragma unroll
    for (int l = 0; l < G; ++l) { int idx = tid + l * 256; brow[l] = idx / F4PR; bc[l] = idx % F4PR; }

    {
        float4 v = *(const float4*)&A[(size_t)(bm + arow) * K + kb + ak4 * 4];
        As2[0][ak4 * 4 + 0][2 * arow] = v.x; As2[0][ak4 * 4 + 0][2 * arow + 1] = v.x;
        As2[0][ak4 * 4 + 1][2 * arow] = v.y; As2[0][ak4 * 4 + 1][2 * arow + 1] = v.y;
        As2[0][ak4 * 4 + 2][2 * arow] = v.z; As2[0][ak4 * 4 + 2][2 * arow + 1] = v.z;
        As2[0][ak4 * 4 + 3][2 * arow] = v.w; As2[0][ak4 * 4 + 3][2 * arow + 1] = v.w;
        #pragma unroll
        for (int l = 0; l < G; ++l)
            *(float4*)&Bs[0][brow[l]][bc[l] * 4] =
                *(const float4*)&B[(size_t)(kb + brow[l]) * N + bn + bc[l] * 4];
    }
    __syncthreads();

    int cur = 0;
    for (int k0 = 0; k0 < k_len; k0 += BK) {
        float4 pa; float4 pb[G];
        bool more = (k0 + BK) < k_len;
        if (more) {
            pa = *(const float4*)&A[(size_t)(bm + arow) * K + kb + k0 + BK + ak4 * 4];
            #pragma unroll
            for (int l = 0; l < G; ++l)
                pb[l] = *(const float4*)&B[(size_t)(kb + k0 + BK + brow[l]) * N + bn + bc[l] * 4];
        }
        #pragma unroll
        for (int k = 0; k < BK; ++k) {
            unsigned long long a2[4];
            #pragma unroll
            for (int r = 0; r < 4; ++r)
                a2[r] = *(const unsigned long long*)&As2[cur][k][2 * (ty * 4 + r)];
            #pragma unroll
            for (int g = 0; g < G; ++g) {
                unsigned long long b0 = *(const unsigned long long*)&Bs[cur][k][g * 64 + tx * 4];
                unsigned long long b1 = *(const unsigned long long*)&Bs[cur][k][g * 64 + tx * 4 + 2];
                #pragma unroll
                for (int r = 0; r < 4; ++r) {
                    fma2(acc[r][g * 2 + 0], a2[r], b0);
                    fma2(acc[r][g * 2 + 1], a2[r], b1);
                }
            }
        }
        int nb = cur ^ 1;
        if (more) {
            As2[nb][ak4 * 4 + 0][2 * arow] = pa.x; As2[nb][ak4 * 4 + 0][2 * arow + 1] = pa.x;
            As2[nb][ak4 * 4 + 1][2 * arow] = pa.y; As2[nb][ak4 * 4 + 1][2 * arow + 1] = pa.y;
            As2[nb][ak4 * 4 + 2][2 * arow] = pa.z; As2[nb][ak4 * 4 + 2][2 * arow + 1] = pa.z;
            As2[nb][ak4 * 4 + 3][2 * arow] = pa.w; As2[nb][ak4 * 4 + 3][2 * arow + 1] = pa.w;
            #pragma unroll
            for (int l = 0; l < G; ++l)
                *(float4*)&Bs[nb][brow[l]][bc[l] * 4] = pb[l];
        }
        __syncthreads();
        cur = nb;
    }

    #pragma unroll
    for (int r = 0; r < 4; ++r) {
        int row = bm + ty * 4 + r;
        #pragma unroll
        for (int g = 0; g < G; ++g) {
            int cbase = bn + g * 64 + tx * 4;
            float4 o;
            o.x = plo(acc[r][g * 2 + 0]); o.y = phi(acc[r][g * 2 + 0]);
            o.z = plo(acc[r][g * 2 + 1]); o.w = phi(acc[r][g * 2 + 1]);
            *(float4*)&P[(size_t)row * N + cbase] = o;
        }
    }
}

// ---------------- split-K reductions ----------------
__global__ __launch_bounds__(256) void red1_kernel(const float* __restrict__ bias) {
    int i = (blockIdx.x * 256 + threadIdx.x) * 4;
    float4 s = *(const float4*)&g_part1[0][i];
    #pragma unroll
    for (int p = 1; p < SPLIT1; ++p) {
        float4 v = *(const float4*)&g_part1[p][i];
        s.x += v.x; s.y += v.y; s.z += v.z; s.w += v.w;
    }
    float4 b = *(const float4*)&bias[i & (HENC - 1)];
    s.x = fmaxf(s.x + b.x, 0.0f); s.y = fmaxf(s.y + b.y, 0.0f);
    s.z = fmaxf(s.z + b.z, 0.0f); s.w = fmaxf(s.w + b.w, 0.0f);
    *(float4*)&g_h1[i] = s;
}
__global__ __launch_bounds__(256) void red2_kernel(const float* __restrict__ bias) {
    int i = (blockIdx.x * 256 + threadIdx.x) * 4;
    float4 s = *(const float4*)&g_part2[0][i];
    #pragma unroll
    for (int p = 1; p < SPLIT2; ++p) {
        float4 v = *(const float4*)&g_part2[p][i];
        s.x += v.x; s.y += v.y; s.z += v.z; s.w += v.w;
    }
    float4 b = *(const float4*)&bias[i & (EMBD - 1)];
    s.x += b.x; s.y += b.y; s.z += b.z; s.w += b.w;
    *(float4*)&g_lat[i] = s;
    __nv_bfloat162 h0 = __floats2bfloat162_rn(s.x, s.y);
    __nv_bfloat162 h1 = __floats2bfloat162_rn(s.z, s.w);
    *(uint2*)&g_lat_bf[i] = make_uint2(*(uint32_t*)&h0, *(uint32_t*)&h1);
}

// ---------------- bf16 tensor-core GEMM (decoder; bf16 B) ----------------
#define PA 40
#define PB 136
template<bool MSE>
__global__ __launch_bounds__(256) void bgemm_b16(
    const __nv_bfloat16* __restrict__ A, const __nv_bfloat16* __restrict__ B,
    const float* __restrict__ bias, __nv_bfloat16* __restrict__ Cb,
    const float* __restrict__ X, int M, int N, int K)
{
    const int BM = 128, BN = 128, BK = 32;
    __shared__ __nv_bfloat16 As[2][BM * PA];
    __shared__ __nv_bfloat16 Bs[2][BK * PB];
    int tid = threadIdx.x;
    int wid = tid >> 5, lane = tid & 31;
    int wm = (wid & 3) * 32, wn = (wid >> 2) * 64;
    int bm = blockIdx.y * BM, bn = blockIdx.x * BN;

    float acc[2][8][4];
    #pragma unroll
    for (int mt = 0; mt < 2; ++mt)
        #pragma unroll
        for (int nt = 0; nt < 8; ++nt)
            #pragma unroll
            for (int e = 0; e < 4; ++e) acc[mt][nt][e] = 0.0f;

    int ar[2], acg[2];
    #pragma unroll
    for (int l = 0; l < 2; ++l) { int idx = tid + l * 256; ar[l] = idx >> 2; acg[l] = idx & 3; }
    int br[2], bcg[2];
    #pragma unroll
    for (int l = 0; l < 2; ++l) { int idx = tid + l * 256; br[l] = idx >> 4; bcg[l] = idx & 15; }

    uint32_t asbase = s2u(&As[0][0]);
    uint32_t bsbase = s2u(&Bs[0][0]);

    #pragma unroll
    for (int l = 0; l < 2; ++l) {
        *(uint4*)&As[0][ar[l] * PA + acg[l] * 8] =
            *(const uint4*)&A[(size_t)(bm + ar[l]) * K + acg[l] * 8];
        *(uint4*)&Bs[0][br[l] * PB + bcg[l] * 8] =
            *(const uint4*)&B[(size_t)br[l] * N + bn + bcg[l] * 8];
    }
    __syncthreads();

    int sub = lane >> 3, lr = lane & 7;
    int cur = 0;
    for (int k0 = 0; k0 < K; k0 += BK) {
        uint4 pa[2], pb[2];
        bool more = (k0 + BK) < K;
        if (more) {
            #pragma unroll
            for (int l = 0; l < 2; ++l) {
                pa[l] = *(const uint4*)&A[(size_t)(bm + ar[l]) * K + k0 + BK + acg[l] * 8];
                pb[l] = *(const uint4*)&B[(size_t)(k0 + BK + br[l]) * N + bn + bcg[l] * 8];
            }
        }
        #pragma unroll
        for (int ks = 0; ks < BK; ks += 16) {
            uint32_t a[2][4], b[8][2];
            #pragma unroll
            for (int mt = 0; mt < 2; ++mt) {
                int row = wm + mt * 16 + (sub & 1) * 8 + lr;
                int kc = ks + (sub >> 1) * 8;
                ldsm4(a[mt], asbase + (uint32_t)(cur * BM * PA + row * PA + kc) * 2);
            }
            #pragma unroll
            for (int ng = 0; ng < 4; ++ng) {
                uint32_t r4[4];
                int krow = ks + (sub & 1) * 8 + lr;
                int ncol = wn + ng * 16 + (sub >> 1) * 8;
                ldsm4t(r4, bsbase + (uint32_t)(cur * BK * PB + krow * PB + ncol) * 2);
                b[ng * 2 + 0][0] = r4[0]; b[ng * 2 + 0][1] = r4[1];
                b[ng * 2 + 1][0] = r4[2]; b[ng * 2 + 1][1] = r4[3];
            }
            #pragma unroll
            for (int mt = 0; mt < 2; ++mt)
                #pragma unroll
                for (int nt = 0; nt < 8; ++nt)
                    mma16816(acc[mt][nt], a[mt], b[nt]);
        }
        int nb = cur ^ 1;
        if (more) {
            #pragma unroll
            for (int l = 0; l < 2; ++l) {
                *(uint4*)&As[nb][ar[l] * PA + acg[l] * 8] = pa[l];
                *(uint4*)&Bs[nb][br[l] * PB + bcg[l] * 8] = pb[l];
            }
        }
        __syncthreads();
        cur = nb;
    }

    float lsum = 0.0f;
    #pragma unroll
    for (int mt = 0; mt < 2; ++mt) {
        int row0 = bm + wm + mt * 16 + (lane >> 2);
        #pragma unroll
        for (int nt = 0; nt < 8; ++nt) {
            int col = bn + wn + nt * 8 + (lane & 3) * 2;
            float b0 = bias[col], b1 = bias[col + 1];
            #pragma unroll
            for (int h = 0; h < 2; ++h) {
                int row = row0 + h * 8;
                float v0 = acc[mt][nt][h * 2 + 0] + b0;
                float v1 = acc[mt][nt][h * 2 + 1] + b1;
                if (!MSE) {
                    v0 = fmaxf(v0, 0.0f); v1 = fmaxf(v1, 0.0f);
                    *(__nv_bfloat162*)&Cb[(size_t)row * N + col] = __floats2bfloat162_rn(v0, v1);
                } else {
                    float2 xv = *(const float2*)&X[(size_t)row * N + col];
                    float d0 = xv.x - v0, d1 = xv.y - v1;
                    lsum = fmaf(d0, d0, lsum);
                    lsum = fmaf(d1, d1, lsum);
                }
            }
        }
    }
    if (MSE) {
        #pragma unroll
        for (int o = 16; o > 0; o >>= 1)
            lsum += __shfl_down_sync(0xffffffffu, lsum, o);
        __shared__ float wsum[8];
        if (lane == 0) wsum[wid] = lsum;
        __syncthreads();
        if (tid == 0) {
            float s = 0.0f;
            #pragma unroll
            for (int w = 0; w < 8; ++w) s += wsum[w];
            atomicAdd(&g_rec, s);
        }
    }
}

// ---------------- pairwise distance matrix per branch ----------------
__global__ __launch_bounds__(256) void dist_kernel() {
    int brz = blockIdx.z;
    int i0 = blockIdx.y * 32, j0 = blockIdx.x * 32;
    __shared__ float Li[32][BRW + 1];
    __shared__ float Lj[32][BRW + 1];
    int t = threadIdx.x;
    #pragma unroll
    for (int l = 0; l < 4; ++l) {
        int idx = t + l * 256;
        int r = idx >> 5, c4 = idx & 31;
        float4 v = *(const float4*)&g_lat[(size_t)(i0 + r) * EMBD + brz * BRW + c4 * 4];
        Li[r][c4 * 4 + 0] = v.x; Li[r][c4 * 4 + 1] = v.y;
        Li[r][c4 * 4 + 2] = v.z; Li[r][c4 * 4 + 3] = v.w;
        float4 w = *(const float4*)&g_lat[(size_t)(j0 + r) * EMBD + brz * BRW + c4 * 4];
        Lj[r][c4 * 4 + 0] = w.x; Lj[r][c4 * 4 + 1] = w.y;
        Lj[r][c4 * 4 + 2] = w.z; Lj[r][c4 * 4 + 3] = w.w;
    }
    __syncthreads();
    int tx = t & 31, ty = t >> 5;
    #pragma unroll
    for (int ii = 0; ii < 4; ++ii) {
        int il = ty * 4 + ii;
        float acc = 0.0f;
        #pragma unroll 16
        for (int k = 0; k < BRW; ++k) {
            float d = Li[il][k] - Lj[tx][k];
            acc = fmaf(d, d, acc);
        }
        g_D[brz][(size_t)(i0 + il) * NPTS + j0 + tx] = sqrtf(acc);
    }
}

// ---------------- Boruvka MST + fused bitonic sort (edges in smem) -----------
__global__ __launch_bounds__(512) void boruvka_kernel() {
    int brz = blockIdx.x;
    const float* __restrict__ D = g_D[brz];
    int i = threadIdx.x;
    __shared__ int comp[NPTS];
    __shared__ unsigned cbw[NPTS];
    __shared__ int cbi[NPTS];
    __shared__ int cbj[NPTS];
    __shared__ int hook0[NPTS];
    __shared__ int hook[NPTS];
    __shared__ float sedge[NPTS];
    __shared__ int nedges;

    comp[i] = i;
    if (i == 0) nedges = 0;

    for (int round = 0; round < 10; ++round) {
        __syncthreads();
        if (nedges >= NPTS - 1) break;
        cbw[i] = 0xFFFFFFFFu;
        cbi[i] = 0x7FFFFFFF;
        __syncthreads();

        int ci = comp[i];
        unsigned bw = 0xFFFFFFFFu; int bj = -1;
        for (int k0 = 0; k0 < NPTS; k0 += 4) {
            int4 c4 = *(const int4*)&comp[k0];
            float w0 = D[(size_t)(k0 + 0) * NPTS + i];
            float w1 = D[(size_t)(k0 + 1) * NPTS + i];
            float w2 = D[(size_t)(k0 + 2) * NPTS + i];
            float w3 = D[(size_t)(k0 + 3) * NPTS + i];
            unsigned u0 = __float_as_uint(w0), u1 = __float_as_uint(w1);
            unsigned u2 = __float_as_uint(w2), u3 = __float_as_uint(w3);
            if (c4.x != ci && u0 < bw) { bw = u0; bj = k0 + 0; }
            if (c4.y != ci && u1 < bw) { bw = u1; bj = k0 + 1; }
            if (c4.z != ci && u2 < bw) { bw = u2; bj = k0 + 2; }
            if (c4.w != ci && u3 < bw) { bw = u3; bj = k0 + 3; }
        }
        if (bj >= 0) atomicMin(&cbw[ci], bw);
        __syncthreads();
        if (bj >= 0 && bw == cbw[ci]) atomicMin(&cbi[ci], i);
        __syncthreads();
        if (bj >= 0 && bw == cbw[ci] && cbi[ci] == i) cbj[ci] = bj;
        __syncthreads();

        bool isroot = (comp[i] == i);
        if (isroot) hook0[i] = (cbw[i] != 0xFFFFFFFFu) ? comp[cbj[i]] : i;
        __syncthreads();
        if (isroot) {
            int d = hook0[i];
            if (d != i) {
                bool mutual = (hook0[d] == i);
                if (!mutual || i < d) {
                    int e = atomicAdd(&nedges, 1);
                    sedge[e] = __uint_as_float(cbw[i]);
                }
                hook[i] = (mutual && i < d) ? i : d;
            } else {
                hook[i] = i;
            }
        }
        __syncthreads();
        #pragma unroll
        for (int s = 0; s < 9; ++s) {
            int h = -1;
            if (isroot) h = hook[hook[i]];
            __syncthreads();
            if (isroot) hook[i] = h;
            __syncthreads();
        }
        comp[i] = hook[comp[i]];
    }

    // fused bitonic sort of the NPTS-1 edges (pad with +inf)
    __syncthreads();
    if (i >= NPTS - 1 || i >= nedges) {
        if (i >= NPTS - 1) sedge[i] = 3.402823466e38f;
    }
    if (i == NPTS - 1) sedge[i] = 3.402823466e38f;
    __syncthreads();
    for (int ksz = 2; ksz <= NPTS; ksz <<= 1) {
        for (int j = ksz >> 1; j > 0; j >>= 1) {
            int ixj = i ^ j;
            if (ixj > i) {
                float a = sedge[i], b = sedge[ixj];
                bool up = ((i & ksz) == 0);
                if ((a > b) == up) { sedge[i] = b; sedge[ixj] = a; }
            }
            __syncthreads();
        }
    }
    g_mst_sorted[brz][i] = sedge[i];
}

// ---------------- connectivity loss (binary search over sorted MST) ----------
__global__ __launch_bounds__(256) void conn_kernel() {
    int brz = blockIdx.y;
    __shared__ float s[NPTS];
    int t = threadIdx.x;
    s[t] = g_mst_sorted[brz][t];
    s[t + 256] = g_mst_sorted[brz][t + 256];
    __syncthreads();
    float lsum = 0.0f;
    for (int p = blockIdx.x * 256 + t; p < NPTS * NPTS; p += gridDim.x * 256) {
        int i = p >> 9, j = p & (NPTS - 1);
        if (j > i) {
            float d = g_D[brz][p];
            float lo = d - 0.004f, hi = d + 0.004f;
            int l = 0, r = NPTS;
            while (l < r) {
                int m = (l + r) >> 1;
                if (s[m] < lo) l = m + 1; else r = m;
            }
            bool hit = false;
            while (l < NPTS - 1 && s[l] <= hi) {
                float m = s[l];
                if (fabsf(d - m) <= ATOL_F + RTOL_F * fabsf(m)) { hit = true; break; }
                ++l;
            }
            if (hit) lsum += fabsf(ETA_F - d);
        }
    }
    #pragma unroll
    for (int o = 16; o > 0; o >>= 1)
        lsum += __shfl_down_sync(0xffffffffu, lsum, o);
    __shared__ float wsum[8];
    if ((t & 31) == 0) wsum[t >> 5] = lsum;
    __syncthreads();
    if (t == 0) {
        float ss = 0.0f;
        #pragma unroll
        for (int w = 0; w < 8; ++w) ss += wsum[w];
        atomicAdd(&g_conn, ss);
    }
}

__global__ void final_kernel(float* out) {
    out[0] = g_rec / (float)((size_t)NPTS * (size_t)DIN) + g_conn;
}

// ---------------- launch ----------------
extern "C" void kernel_launch(void* const* d_in, const int* in_sizes, int n_in,
                              void* d_out, int out_size) {
    const float* x   = (const float*)d_in[0];
    const float* We1 = (const float*)d_in[1];
    const float* be1 = (const float*)d_in[2];
    const float* We2 = (const float*)d_in[3];
    const float* be2 = (const float*)d_in[4];
    const float* Wd1 = (const float*)d_in[5];
    const float* bd1 = (const float*)d_in[6];
    const float* Wd2 = (const float*)d_in[7];
    const float* bd2 = (const float*)d_in[8];
    float* out = (float*)d_out;

    float *h1, *p1, *p2;
    __nv_bfloat16 *latb, *h2b, *xhi, *xlo, *w1hi, *w1lo, *wd1b, *wd2b;
    cudaGetSymbolAddress((void**)&h1,   g_h1);
    cudaGetSymbolAddress((void**)&p1,   g_part1);
    cudaGetSymbolAddress((void**)&p2,   g_part2);
    cudaGetSymbolAddress((void**)&latb, g_lat_bf);
    cudaGetSymbolAddress((void**)&h2b,  g_h2b);
    cudaGetSymbolAddress((void**)&xhi,  g_xhi);
    cudaGetSymbolAddress((void**)&xlo,  g_xlo);
    cudaGetSymbolAddress((void**)&w1hi, g_w1hi);
    cudaGetSymbolAddress((void**)&w1lo, g_w1lo);
    cudaGetSymbolAddress((void**)&wd1b, g_wd1b);
    cudaGetSymbolAddress((void**)&wd2b, g_wd2b);

    static cudaStream_t s_top = nullptr;
    static cudaEvent_t ev_fork0 = nullptr, ev_fork = nullptr, ev_join = nullptr,
                       ev_cvt = nullptr, ev_wd = nullptr;
    if (s_top == nullptr) {
        cudaStreamCreate(&s_top);
        cudaEventCreateWithFlags(&ev_fork0, cudaEventDisableTiming);
        cudaEventCreateWithFlags(&ev_fork,  cudaEventDisableTiming);
        cudaEventCreateWithFlags(&ev_join,  cudaEventDisableTiming);
        cudaEventCreateWithFlags(&ev_cvt,   cudaEventDisableTiming);
        cudaEventCreateWithFlags(&ev_wd,    cudaEventDisableTiming);
    }

    zero_kernel<<<1, 1>>>();
    cudaEventRecord(ev_fork0, 0);
    cudaStreamWaitEvent(s_top, ev_fork0, 0);
    // side stream: We1 hi/lo cvt, then decoder weight cvts (hidden under GEMM1)
    cvt_split<<<(DIN * HENC) / 2048, 256, 0, s_top>>>(We1, w1hi, w1lo, DIN * HENC);
    cudaEventRecord(ev_cvt, s_top);
    cvt_bf16<<<(EMBD * HDEC) / 2048, 256, 0, s_top>>>(Wd1, wd1b, EMBD * HDEC);
    cvt_bf16<<<(HDEC * DIN) / 2048, 256, 0, s_top>>>(Wd2, wd2b, HDEC * DIN);
    cudaEventRecord(ev_wd, s_top);
    // main stream: x hi/lo cvt concurrent with We1 cvt
    cvt_split<<<(NPTS * DIN) / 2048, 256>>>(x, xhi, xlo, NPTS * DIN);
    cudaStreamWaitEvent(0, ev_cvt, 0);
    // encoder GEMM1: bf16x3 tensor cores, split-K 8 (monolithic, R14-proven)
    bgemm3_split<<<dim3(HENC / 128, NPTS / 128, SPLIT1), 256>>>(
        xhi, xlo, w1hi, w1lo, p1, NPTS, HENC, DIN, DIN / SPLIT1);
    red1_kernel<<<NPTS * HENC / 1024, 256>>>(be1);
    // encoder GEMM2: fp32 FFMA2 split-K (precision safety)
    sgemm_split<1><<<dim3(EMBD / 64, NPTS / 64, SPLIT2), 256>>>(h1, We2, p2, NPTS, EMBD, HENC, HENC / SPLIT2);
    red2_kernel<<<NPTS * EMBD / 1024, 256>>>(be2);

    // fork: topology chain on side stream, decoder on main stream
    cudaEventRecord(ev_fork, 0);
    cudaStreamWaitEvent(s_top, ev_fork, 0);
    dist_kernel<<<dim3(NPTS / 32, NPTS / 32, NBRANCH), 256, 0, s_top>>>();
    boruvka_kernel<<<NBRANCH, NPTS, 0, s_top>>>();
    conn_kernel<<<dim3(64, NBRANCH), 256, 0, s_top>>>();
    cudaEventRecord(ev_join, s_top);

    cudaStreamWaitEvent(0, ev_wd, 0);
    bgemm_b16<false><<<dim3(HDEC / 128, NPTS / 128), 256>>>(latb, wd1b, bd1, h2b, nullptr, NPTS, HDEC, EMBD);
    bgemm_b16<true ><<<dim3(DIN  / 128, NPTS / 128), 256>>>(h2b,  wd2b, bd2, nullptr, x,   NPTS, DIN,  HDEC);

    cudaStreamWaitEvent(0, ev_join, 0);
    final_kernel<<<1, 1>>>(out);
}